// round 14
// baseline (speedup 1.0000x reference)
#include <cuda_runtime.h>
#include <cuda_fp16.h>
#include <math.h>
#include <stdint.h>

#define TTOK   2048
#define HDIM   768
#define NEXP   8
#define IDIM   768
#define MAXP   (TTOK*2)
#define ALPHA  1.702f
#define LIMIT  7.0f
#define BK     32
#define NCH    (HDIM / BK)   // 24
#define NSTG_G 3
#define NSTG_D 4

// -------- scratch --------
__device__ int    g_cnt[NEXP];
__device__ int    g_list[NEXP * MAXP];
__device__ float  g_w[TTOK * 2];
__device__ __half g_xh[(size_t)TTOK * HDIM];        // fp16 x
__device__ __half g_acth[(size_t)TTOK * 2 * IDIM];  // fp16 activations

// ------------------------- helpers -------------------------
__device__ __forceinline__ uint32_t h2u(__half2 h) {
    union { __half2 h; uint32_t u; } v; v.h = h; return v.u;
}
__device__ __forceinline__ uint32_t packh(float lo, float hi) {
    return h2u(__floats2half2_rn(lo, hi));
}
__device__ __forceinline__ void mma16(float* d, const uint32_t* a, const uint32_t* b) {
    asm volatile(
        "mma.sync.aligned.m16n8k16.row.col.f32.f16.f16.f32 "
        "{%0,%1,%2,%3}, {%4,%5,%6,%7}, {%8,%9}, {%0,%1,%2,%3};"
        : "+f"(d[0]), "+f"(d[1]), "+f"(d[2]), "+f"(d[3])
        : "r"(a[0]), "r"(a[1]), "r"(a[2]), "r"(a[3]), "r"(b[0]), "r"(b[1]));
}
__device__ __forceinline__ uint32_t smem_u32(const void* p) {
    uint32_t a;
    asm("{ .reg .u64 t; cvta.to.shared.u64 t, %1; cvt.u32.u64 %0, t; }"
        : "=r"(a) : "l"(p));
    return a;
}
__device__ __forceinline__ void cp16(uint32_t dst, const void* src, int sz) {
    asm volatile("cp.async.cg.shared.global [%0], [%1], 16, %2;"
                 :: "r"(dst), "l"(src), "r"(sz));
}
#define CP_COMMIT() asm volatile("cp.async.commit_group;" ::: "memory")
#define CP_WAIT(n)  asm volatile("cp.async.wait_group %0;" :: "n"(n) : "memory")
__device__ __forceinline__ void ldsm4(uint32_t* r, uint32_t addr) {
    asm volatile("ldmatrix.sync.aligned.m8n8.x4.shared.b16 {%0,%1,%2,%3}, [%4];"
                 : "=r"(r[0]), "=r"(r[1]), "=r"(r[2]), "=r"(r[3]) : "r"(addr));
}
__device__ __forceinline__ void red2(float* p, float v0, float v1) {
    asm volatile("red.global.add.v2.f32 [%0], {%1, %2};"
                 :: "l"(p), "f"(v0), "f"(v1) : "memory");
}

// A tile: 128 x 32 halves, row 64B + 16 pad = 80B
// down B tile: 32 x 64 fp32, row 256B + 16 = 272B (68 words)
// gu B tile (per plane): 32 x 32 fp32, row 128B + 16 = 144B (36 words)
#define A_ROWB   80
#define A_BYTES  (128 * A_ROWB)       // 10240
#define BD_ROWW  68
#define BD_BYTES (32 * BD_ROWW * 4)   // 8704
#define BG_ROWW  36
#define BG_BYTES (32 * BG_ROWW * 4)   // 4608
#define DN_STAGE (A_BYTES + BD_BYTES)       // 18944
#define GU_STAGE (A_BYTES + 2 * BG_BYTES)   // 19456

// ------------------------------ init (counters) ------------------------------
__global__ void zero_cnt_kernel() {
    if (threadIdx.x < NEXP) g_cnt[threadIdx.x] = 0;
}

// ------------------- router (+ zero out rows, + x -> fp16) -------------------
__global__ __launch_bounds__(256) void router_kernel(
    const float* __restrict__ x, const float* __restrict__ Wr,
    const float* __restrict__ br, float* __restrict__ out)
{
    {
        float4* ob = (float4*)(out + (size_t)blockIdx.x * 8 * HDIM);
#pragma unroll
        for (int i = 0; i < 6; i++)
            ob[threadIdx.x + i * 256] = make_float4(0.f, 0.f, 0.f, 0.f);
    }

    int warp = threadIdx.x >> 5;
    int lane = threadIdx.x & 31;
    int t = blockIdx.x * 8 + warp;

    const float4* xr = (const float4*)(x + (size_t)t * HDIM);
    __half2* xo = (__half2*)(g_xh + (size_t)t * HDIM);
    float acc[NEXP];
#pragma unroll
    for (int e = 0; e < NEXP; e++) acc[e] = 0.f;

#pragma unroll
    for (int i = 0; i < 6; i++) {
        int h4 = lane + i * 32;
        float4 xv = xr[h4];
        xo[h4 * 2]     = __floats2half2_rn(xv.x, xv.y);
        xo[h4 * 2 + 1] = __floats2half2_rn(xv.z, xv.w);
        const float* w = Wr + h4 * 4 * NEXP;
#pragma unroll
        for (int e = 0; e < NEXP; e++) {
            float s = fmaf(xv.x, w[e], 0.f);
            s = fmaf(xv.y, w[e + 8], s);
            s = fmaf(xv.z, w[e + 16], s);
            s = fmaf(xv.w, w[e + 24], s);
            acc[e] += s;
        }
    }
#pragma unroll
    for (int e = 0; e < NEXP; e++) {
#pragma unroll
        for (int o = 16; o > 0; o >>= 1)
            acc[e] += __shfl_xor_sync(0xffffffffu, acc[e], o);
    }
    if (lane == 0) {
#pragma unroll
        for (int e = 0; e < NEXP; e++) acc[e] += br[e];

        int i0 = 0; float v0 = acc[0];
#pragma unroll
        for (int e = 1; e < NEXP; e++)
            if (acc[e] > v0) { v0 = acc[e]; i0 = e; }
        int i1 = -1; float v1 = -INFINITY;
#pragma unroll
        for (int e = 0; e < NEXP; e++)
            if (e != i0 && acc[e] > v1) { v1 = acc[e]; i1 = e; }

        float s1 = expf(v1 - v0);
        float d  = 1.f + s1;
        g_w[t * 2 + 0] = 1.f / d;
        g_w[t * 2 + 1] = s1 / d;

        int p0 = atomicAdd(&g_cnt[i0], 1);
        g_list[i0 * MAXP + p0] = t * 2;
        int p1 = atomicAdd(&g_cnt[i1], 1);
        g_list[i1 * MAXP + p1] = t * 2 + 1;
    }
}

// =============== stage 1: gate/up GEMM (fp32 B direct) + SwiGLU ===============
// block 128 x (32 gate | 32 up), 8 warps 4Mx2N, warp 32x16 per plane.
__global__ __launch_bounds__(256, 3) void gu_mma(
    const float* __restrict__ Wgu, const float* __restrict__ bgu)
{
    int e   = blockIdx.z;
    int cnt = g_cnt[e];
    int m0  = blockIdx.y * 128;
    if (m0 >= cnt) return;
    int n0  = blockIdx.x * 32;   // per-plane column base

    extern __shared__ __align__(16) char dsm[];
    __shared__ int sSlot[128];

    int tid  = threadIdx.x;
    int wid  = tid >> 5, lane = tid & 31;
    int wM   = wid >> 1, wN = wid & 1;
    int gID  = lane >> 2, tg = lane & 3;

    for (int m = tid; m < 128; m += 256) {
        int idx = m0 + m;
        sSlot[m] = (idx < cnt) ? g_list[e * MAXP + idx] : -1;
    }
    __syncthreads();

    const float* Wg = Wgu + (size_t)e * HDIM * (2 * IDIM);
    uint32_t smb = smem_u32(dsm);
    uint32_t aOff = (uint32_t)(wM * 32 * A_ROWB + (lane & 15) * A_ROWB + (lane >> 4) * 16);

    const __half* aSrc[2]; int aSz[2]; uint32_t aDst[2];
#pragma unroll
    for (int i = 0; i < 2; i++) {
        int idx = tid + i * 256;
        int m = idx >> 2, kq = idx & 3;
        int slot = sSlot[m];
        aSrc[i] = (slot >= 0) ? g_xh + (size_t)(slot >> 1) * HDIM + kq * 8 : g_xh;
        aSz[i]  = (slot >= 0) ? 16 : 0;
        aDst[i] = (uint32_t)(m * A_ROWB + kq * 16);
    }
    // B: 2 planes x 32 rows x 128B = 512 cp16 -> 2 per thread
    const float* bSrc[2]; uint32_t bDst[2];
#pragma unroll
    for (int i = 0; i < 2; i++) {
        int idx = tid + i * 256;
        int plane = idx >> 8, k = (idx >> 3) & 31, n4 = idx & 7;
        bSrc[i] = Wg + (size_t)k * (2 * IDIM) + plane * IDIM + n0 + n4 * 4;
        bDst[i] = (uint32_t)(plane * BG_BYTES + (k * BG_ROWW + n4 * 4) * 4);
    }

    float accG[2][2][4], accU[2][2][4];
#pragma unroll
    for (int mt = 0; mt < 2; mt++)
#pragma unroll
        for (int nt = 0; nt < 2; nt++)
#pragma unroll
            for (int q = 0; q < 4; q++) { accG[mt][nt][q] = 0.f; accU[mt][nt][q] = 0.f; }

#define GU_ISSUE(c) do {                                                       \
    uint32_t st = smb + (uint32_t)((c) % NSTG_G) * GU_STAGE;                   \
    int k0 = (c) * BK;                                                         \
    _Pragma("unroll")                                                          \
    for (int i = 0; i < 2; i++) cp16(st + aDst[i], aSrc[i] + k0, aSz[i]);      \
    _Pragma("unroll")                                                          \
    for (int i = 0; i < 2; i++)                                                \
        cp16(st + A_BYTES + bDst[i], bSrc[i] + (size_t)k0 * (2 * IDIM), 16);   \
    } while (0)

    GU_ISSUE(0); CP_COMMIT();
    GU_ISSUE(1); CP_COMMIT();

    int colw = wN * 16 + gID;   // word column within plane tile (nt adds 8)
    for (int c = 0; c < NCH; c++) {
        CP_WAIT(1);
        __syncthreads();
        if (c + 2 < NCH) GU_ISSUE(c + 2);
        CP_COMMIT();

        uint32_t stA = smb + (uint32_t)(c % NSTG_G) * GU_STAGE;
        const float* fBg = (const float*)(dsm + (c % NSTG_G) * GU_STAGE + A_BYTES);
        const float* fBu = fBg + BG_BYTES / 4;

#pragma unroll
        for (int s = 0; s < 2; s++) {           // two k16 steps per 32-chunk
            uint32_t a[2][4];
#pragma unroll
            for (int mt = 0; mt < 2; mt++)
                ldsm4(a[mt], stA + aOff + (uint32_t)(mt * 16 * A_ROWB + s * 32));
            int kb = s * 16 + 2 * tg;
#pragma unroll
            for (int nt = 0; nt < 2; nt++) {
                int cw = colw + nt * 8;
                uint32_t bg[2], bu[2];
                bg[0] = packh(fBg[kb * BG_ROWW + cw],       fBg[(kb + 1) * BG_ROWW + cw]);
                bg[1] = packh(fBg[(kb + 8) * BG_ROWW + cw], fBg[(kb + 9) * BG_ROWW + cw]);
                bu[0] = packh(fBu[kb * BG_ROWW + cw],       fBu[(kb + 1) * BG_ROWW + cw]);
                bu[1] = packh(fBu[(kb + 8) * BG_ROWW + cw], fBu[(kb + 9) * BG_ROWW + cw]);
#pragma unroll
                for (int mt = 0; mt < 2; mt++) {
                    mma16(accG[mt][nt], a[mt], bg);
                    mma16(accU[mt][nt], a[mt], bu);
                }
            }
        }
    }

    // ---- epilogue: bias + clamp + SwiGLU -> fp16 g_acth ----
    const float* bge = bgu + (size_t)e * (2 * IDIM);
#pragma unroll
    for (int mt = 0; mt < 2; mt++) {
#pragma unroll
        for (int half = 0; half < 2; half++) {
            int row = wM * 32 + mt * 16 + half * 8 + gID;
            int slot = sSlot[row];
            if (slot < 0) continue;
            __half* outp = g_acth + (size_t)slot * IDIM;
#pragma unroll
            for (int nt = 0; nt < 2; nt++) {
                int col = n0 + wN * 16 + nt * 8 + 2 * tg;
                float g0 = accG[mt][nt][half * 2 + 0] + bge[col];
                float g1 = accG[mt][nt][half * 2 + 1] + bge[col + 1];
                float u0 = accU[mt][nt][half * 2 + 0] + bge[IDIM + col];
                float u1 = accU[mt][nt][half * 2 + 1] + bge[IDIM + col + 1];
                g0 = fminf(g0, LIMIT); g1 = fminf(g1, LIMIT);
                u0 = fmaxf(fminf(u0, LIMIT), -LIMIT);
                u1 = fmaxf(fminf(u1, LIMIT), -LIMIT);
                float s0 = 1.f / (1.f + expf(-ALPHA * g0));
                float s1 = 1.f / (1.f + expf(-ALPHA * g1));
                *(__half2*)(outp + col) =
                    __floats2half2_rn((u0 + 1.f) * (g0 * s0), (u1 + 1.f) * (g1 * s1));
            }
        }
    }
}

// =============== stage 2: down GEMM (fp32 B direct) + weighted red.v2 ===============
// block 128 x 64, 8 warps 4Mx2N, warp 32x32.
__global__ __launch_bounds__(256, 3) void down_mma(
    const float* __restrict__ Wd, const float* __restrict__ bd,
    float* __restrict__ out)
{
    int e   = blockIdx.z;
    int cnt = g_cnt[e];
    int m0  = blockIdx.y * 128;
    if (m0 >= cnt) return;
    int n0  = blockIdx.x * 64;

    extern __shared__ __align__(16) char dsm[];
    __shared__ int sSlot[128];

    int tid  = threadIdx.x;
    int wid  = tid >> 5, lane = tid & 31;
    int wM   = wid >> 1, wN = wid & 1;
    int gID  = lane >> 2, tg = lane & 3;

    for (int m = tid; m < 128; m += 256) {
        int idx = m0 + m;
        sSlot[m] = (idx < cnt) ? g_list[e * MAXP + idx] : -1;
    }
    __syncthreads();

    const float* We = Wd + (size_t)e * IDIM * HDIM;
    uint32_t smb = smem_u32(dsm);
    uint32_t aOff = (uint32_t)(wM * 32 * A_ROWB + (lane & 15) * A_ROWB + (lane >> 4) * 16);

    const __half* aSrc[2]; int aSz[2]; uint32_t aDst[2];
#pragma unroll
    for (int i = 0; i < 2; i++) {
        int idx = tid + i * 256;
        int m = idx >> 2, kq = idx & 3;
        int slot = sSlot[m];
        aSrc[i] = (slot >= 0) ? g_acth + (size_t)slot * IDIM + kq * 8 : g_acth;
        aSz[i]  = (slot >= 0) ? 16 : 0;
        aDst[i] = (uint32_t)(m * A_ROWB + kq * 16);
    }
    // B: 32 rows x 256B = 512 cp16 -> 2 per thread
    const float* bSrc[2]; uint32_t bDst[2];
#pragma unroll
    for (int i = 0; i < 2; i++) {
        int idx = tid + i * 256;
        int k = idx >> 4, n4 = idx & 15;
        bSrc[i] = We + (size_t)k * HDIM + n0 + n4 * 4;
        bDst[i] = (uint32_t)((k * BD_ROWW + n4 * 4) * 4);
    }

    float acc[2][4][4];
#pragma unroll
    for (int mt = 0; mt < 2; mt++)
#pragma unroll
        for (int nt = 0; nt < 4; nt++)
#pragma unroll
            for (int q = 0; q < 4; q++) acc[mt][nt][q] = 0.f;

#define DN_ISSUE(c) do {                                                       \
    uint32_t st = smb + (uint32_t)((c) % NSTG_D) * DN_STAGE;                   \
    int k0 = (c) * BK;                                                         \
    _Pragma("unroll")                                                          \
    for (int i = 0; i < 2; i++) cp16(st + aDst[i], aSrc[i] + k0, aSz[i]);      \
    _Pragma("unroll")                                                          \
    for (int i = 0; i < 2; i++)                                                \
        cp16(st + A_BYTES + bDst[i], bSrc[i] + (size_t)k0 * HDIM, 16);         \
    } while (0)

    DN_ISSUE(0); CP_COMMIT();
    DN_ISSUE(1); CP_COMMIT();
    DN_ISSUE(2); CP_COMMIT();

    int colw = wN * 32 + gID;   // word column within B tile (nt adds 8)
    for (int c = 0; c < NCH; c++) {
        CP_WAIT(2);
        __syncthreads();
        if (c + 3 < NCH) DN_ISSUE(c + 3);
        CP_COMMIT();

        uint32_t stA = smb + (uint32_t)(c % NSTG_D) * DN_STAGE;
        const float* fB = (const float*)(dsm + (c % NSTG_D) * DN_STAGE + A_BYTES);

#pragma unroll
        for (int s = 0; s < 2; s++) {
            uint32_t a[2][4];
#pragma unroll
            for (int mt = 0; mt < 2; mt++)
                ldsm4(a[mt], stA + aOff + (uint32_t)(mt * 16 * A_ROWB + s * 32));
            int kb = s * 16 + 2 * tg;
#pragma unroll
            for (int nt = 0; nt < 4; nt++) {
                int cw = colw + nt * 8;
                uint32_t b[2];
                b[0] = packh(fB[kb * BD_ROWW + cw],       fB[(kb + 1) * BD_ROWW + cw]);
                b[1] = packh(fB[(kb + 8) * BD_ROWW + cw], fB[(kb + 9) * BD_ROWW + cw]);
#pragma unroll
                for (int mt = 0; mt < 2; mt++)
                    mma16(acc[mt][nt], a[mt], b);
            }
        }
    }

    // ---- epilogue: weighted vector reduction into out ----
    const float* bde = bd + (size_t)e * HDIM;
#pragma unroll
    for (int mt = 0; mt < 2; mt++) {
#pragma unroll
        for (int half = 0; half < 2; half++) {
            int row = wM * 32 + mt * 16 + half * 8 + gID;
            int slot = sSlot[row];
            if (slot < 0) continue;
            float w = g_w[slot];
            float* outp = out + (size_t)(slot >> 1) * HDIM;
#pragma unroll
            for (int nt = 0; nt < 4; nt++) {
                int col = n0 + wN * 32 + nt * 8 + 2 * tg;
                red2(outp + col,
                     w * (acc[mt][nt][half * 2 + 0] + bde[col]),
                     w * (acc[mt][nt][half * 2 + 1] + bde[col + 1]));
            }
        }
    }
}

// ------------------------------ launch ------------------------------
extern "C" void kernel_launch(void* const* d_in, const int* in_sizes, int n_in,
                              void* d_out, int out_size)
{
    const float* x   = (const float*)d_in[0];
    const float* Wr  = (const float*)d_in[1];
    const float* br  = (const float*)d_in[2];
    const float* Wgu = (const float*)d_in[3];
    const float* bgu = (const float*)d_in[4];
    const float* Wd  = (const float*)d_in[5];
    const float* bd  = (const float*)d_in[6];
    float* out = (float*)d_out;

    const int GU_SMEM = NSTG_G * GU_STAGE;   // 58368
    const int DN_SMEM = NSTG_D * DN_STAGE;   // 75776
    cudaFuncSetAttribute(gu_mma,   cudaFuncAttributeMaxDynamicSharedMemorySize, GU_SMEM);
    cudaFuncSetAttribute(down_mma, cudaFuncAttributeMaxDynamicSharedMemorySize, DN_SMEM);

    zero_cnt_kernel<<<1, 32>>>();
    router_kernel<<<TTOK / 8, 256>>>(x, Wr, br, out);

    dim3 ggrid(IDIM / 32, MAXP / 128, NEXP);   // (24, 32, 8)
    gu_mma<<<ggrid, 256, GU_SMEM>>>(Wgu, bgu);

    dim3 dgrid(HDIM / 64, MAXP / 128, NEXP);   // (12, 32, 8)
    down_mma<<<dgrid, 256, DN_SMEM>>>(Wd, bd, out);
}

// round 15
// speedup vs baseline: 1.1056x; 1.1056x over previous
#include <cuda_runtime.h>
#include <cuda_fp16.h>
#include <math.h>
#include <stdint.h>

#define TTOK   2048
#define HDIM   768
#define NEXP   8
#define IDIM   768
#define MAXP   (TTOK*2)
#define ALPHA  1.702f
#define LIMIT  7.0f
#define BK     32
#define NCH    (HDIM / BK)   // 24
#define NSTG_G 4
#define NSTG_D 4

#define WGU_N  (NEXP * HDIM * 2 * IDIM)   // 9437184

// -------- scratch --------
__device__ int    g_cnt[NEXP];
__device__ int    g_list[NEXP * MAXP];
__device__ float  g_w[TTOK * 2];
__device__ __half g_xh[(size_t)TTOK * HDIM];        // fp16 x
__device__ __half g_acth[(size_t)TTOK * 2 * IDIM];  // fp16 activations
__device__ __half g_wguh[WGU_N];                    // fp16 Wgu

// ------------------------- helpers -------------------------
__device__ __forceinline__ uint32_t h2u(__half2 h) {
    union { __half2 h; uint32_t u; } v; v.h = h; return v.u;
}
__device__ __forceinline__ uint32_t packh(float lo, float hi) {
    return h2u(__floats2half2_rn(lo, hi));
}
__device__ __forceinline__ void mma16(float* d, const uint32_t* a, const uint32_t* b) {
    asm volatile(
        "mma.sync.aligned.m16n8k16.row.col.f32.f16.f16.f32 "
        "{%0,%1,%2,%3}, {%4,%5,%6,%7}, {%8,%9}, {%0,%1,%2,%3};"
        : "+f"(d[0]), "+f"(d[1]), "+f"(d[2]), "+f"(d[3])
        : "r"(a[0]), "r"(a[1]), "r"(a[2]), "r"(a[3]), "r"(b[0]), "r"(b[1]));
}
__device__ __forceinline__ uint32_t smem_u32(const void* p) {
    uint32_t a;
    asm("{ .reg .u64 t; cvta.to.shared.u64 t, %1; cvt.u32.u64 %0, t; }"
        : "=r"(a) : "l"(p));
    return a;
}
__device__ __forceinline__ void cp16(uint32_t dst, const void* src, int sz) {
    asm volatile("cp.async.cg.shared.global [%0], [%1], 16, %2;"
                 :: "r"(dst), "l"(src), "r"(sz));
}
#define CP_COMMIT() asm volatile("cp.async.commit_group;" ::: "memory")
#define CP_WAIT(n)  asm volatile("cp.async.wait_group %0;" :: "n"(n) : "memory")
__device__ __forceinline__ void ldsm4(uint32_t* r, uint32_t addr) {
    asm volatile("ldmatrix.sync.aligned.m8n8.x4.shared.b16 {%0,%1,%2,%3}, [%4];"
                 : "=r"(r[0]), "=r"(r[1]), "=r"(r[2]), "=r"(r[3]) : "r"(addr));
}
__device__ __forceinline__ void ldsm2t(uint32_t* r, uint32_t addr) {
    asm volatile("ldmatrix.sync.aligned.m8n8.x2.trans.shared.b16 {%0,%1}, [%2];"
                 : "=r"(r[0]), "=r"(r[1]) : "r"(addr));
}
__device__ __forceinline__ void red2(float* p, float v0, float v1) {
    asm volatile("red.global.add.v2.f32 [%0], {%1, %2};"
                 :: "l"(p), "f"(v0), "f"(v1) : "memory");
}

// A tile: 128 x 32 halves, row 64B + 16 pad = 80B
#define A_ROWB   80
#define A_BYTES  (128 * A_ROWB)       // 10240
// gu B tile (fp16): 32 x 32 halves, row 64B + 16 = 80B, two planes
#define BG_ROWB  80
#define BG_BYTES (32 * BG_ROWB)       // 2560
#define GU_STAGE (A_BYTES + 2 * BG_BYTES)   // 15360
// down B tile (fp32 direct): 32 x 64 fp32, row 256B + 16 = 272B (68 words)
#define BD_ROWW  68
#define BD_BYTES (32 * BD_ROWW * 4)   // 8704
#define DN_STAGE (A_BYTES + BD_BYTES)       // 18944

// ---------------- prep: Wgu -> fp16 (+ zero counters) ----------------
__global__ __launch_bounds__(256) void prep_kernel(const float* __restrict__ Wgu)
{
    size_t idx = (size_t)blockIdx.x * 256 + threadIdx.x;
    if (idx < NEXP) g_cnt[idx] = 0;
    if (idx >= WGU_N / 8) return;
    const float4* src = (const float4*)Wgu;
    float4 a = src[idx * 2], b = src[idx * 2 + 1];
    ((uint4*)g_wguh)[idx] = make_uint4(packh(a.x, a.y), packh(a.z, a.w),
                                       packh(b.x, b.y), packh(b.z, b.w));
}

// ------------------- router (+ zero out rows, + x -> fp16) -------------------
__global__ __launch_bounds__(256) void router_kernel(
    const float* __restrict__ x, const float* __restrict__ Wr,
    const float* __restrict__ br, float* __restrict__ out)
{
    {
        float4* ob = (float4*)(out + (size_t)blockIdx.x * 8 * HDIM);
#pragma unroll
        for (int i = 0; i < 6; i++)
            ob[threadIdx.x + i * 256] = make_float4(0.f, 0.f, 0.f, 0.f);
    }

    int warp = threadIdx.x >> 5;
    int lane = threadIdx.x & 31;
    int t = blockIdx.x * 8 + warp;

    const float4* xr = (const float4*)(x + (size_t)t * HDIM);
    __half2* xo = (__half2*)(g_xh + (size_t)t * HDIM);
    float acc[NEXP];
#pragma unroll
    for (int e = 0; e < NEXP; e++) acc[e] = 0.f;

#pragma unroll
    for (int i = 0; i < 6; i++) {
        int h4 = lane + i * 32;
        float4 xv = xr[h4];
        xo[h4 * 2]     = __floats2half2_rn(xv.x, xv.y);
        xo[h4 * 2 + 1] = __floats2half2_rn(xv.z, xv.w);
        const float* w = Wr + h4 * 4 * NEXP;
#pragma unroll
        for (int e = 0; e < NEXP; e++) {
            float s = fmaf(xv.x, w[e], 0.f);
            s = fmaf(xv.y, w[e + 8], s);
            s = fmaf(xv.z, w[e + 16], s);
            s = fmaf(xv.w, w[e + 24], s);
            acc[e] += s;
        }
    }
#pragma unroll
    for (int e = 0; e < NEXP; e++) {
#pragma unroll
        for (int o = 16; o > 0; o >>= 1)
            acc[e] += __shfl_xor_sync(0xffffffffu, acc[e], o);
    }
    if (lane == 0) {
#pragma unroll
        for (int e = 0; e < NEXP; e++) acc[e] += br[e];

        int i0 = 0; float v0 = acc[0];
#pragma unroll
        for (int e = 1; e < NEXP; e++)
            if (acc[e] > v0) { v0 = acc[e]; i0 = e; }
        int i1 = -1; float v1 = -INFINITY;
#pragma unroll
        for (int e = 0; e < NEXP; e++)
            if (e != i0 && acc[e] > v1) { v1 = acc[e]; i1 = e; }

        float s1 = expf(v1 - v0);
        float d  = 1.f + s1;
        g_w[t * 2 + 0] = 1.f / d;
        g_w[t * 2 + 1] = s1 / d;

        int p0 = atomicAdd(&g_cnt[i0], 1);
        g_list[i0 * MAXP + p0] = t * 2;
        int p1 = atomicAdd(&g_cnt[i1], 1);
        g_list[i1 * MAXP + p1] = t * 2 + 1;
    }
}

// =============== stage 1: fp16 gate/up GEMM + SwiGLU (R12 config) ===============
// block 128 x (32 gate | 32 up), 8 warps 4Mx2N, warp 32x16 per plane.
__global__ __launch_bounds__(256, 3) void gu_mma(const float* __restrict__ bgu)
{
    int e   = blockIdx.z;
    int cnt = g_cnt[e];
    int m0  = blockIdx.y * 128;
    if (m0 >= cnt) return;
    int n0  = blockIdx.x * 32;   // per-plane column base

    extern __shared__ __align__(16) char dsm[];
    __shared__ int sSlot[128];

    int tid  = threadIdx.x;
    int wid  = tid >> 5, lane = tid & 31;
    int wM   = wid >> 1, wN = wid & 1;
    int gID  = lane >> 2, tg = lane & 3;

    for (int m = tid; m < 128; m += 256) {
        int idx = m0 + m;
        sSlot[m] = (idx < cnt) ? g_list[e * MAXP + idx] : -1;
    }
    __syncthreads();

    const __half* Wg = g_wguh + (size_t)e * HDIM * (2 * IDIM);
    uint32_t smb = smem_u32(dsm);
    uint32_t aOff = (uint32_t)(wM * 32 * A_ROWB + (lane & 15) * A_ROWB + (lane >> 4) * 16);
    uint32_t bOff = (uint32_t)((lane & 15) * BG_ROWB + wN * 32);

    const __half* aSrc[2]; int aSz[2]; uint32_t aDst[2];
#pragma unroll
    for (int i = 0; i < 2; i++) {
        int idx = tid + i * 256;
        int m = idx >> 2, kq = idx & 3;
        int slot = sSlot[m];
        aSrc[i] = (slot >= 0) ? g_xh + (size_t)(slot >> 1) * HDIM + kq * 8 : g_xh;
        aSz[i]  = (slot >= 0) ? 16 : 0;
        aDst[i] = (uint32_t)(m * A_ROWB + kq * 16);
    }
    const __half* bSrc; uint32_t bDst;
    {
        int plane = tid >> 7, k = (tid >> 2) & 31, n16 = tid & 3;
        bSrc = Wg + (size_t)k * (2 * IDIM) + plane * IDIM + n0 + n16 * 8;
        bDst = (uint32_t)(plane * BG_BYTES + k * BG_ROWB + n16 * 16);
    }

    float accG[2][2][4], accU[2][2][4];
#pragma unroll
    for (int mt = 0; mt < 2; mt++)
#pragma unroll
        for (int nt = 0; nt < 2; nt++)
#pragma unroll
            for (int q = 0; q < 4; q++) { accG[mt][nt][q] = 0.f; accU[mt][nt][q] = 0.f; }

#define GU_ISSUE(c) do {                                                       \
    uint32_t st = smb + (uint32_t)((c) % NSTG_G) * GU_STAGE;                   \
    int k0 = (c) * BK;                                                         \
    _Pragma("unroll")                                                          \
    for (int i = 0; i < 2; i++) cp16(st + aDst[i], aSrc[i] + k0, aSz[i]);      \
    cp16(st + A_BYTES + bDst, bSrc + (size_t)k0 * (2 * IDIM), 16);             \
    } while (0)

    GU_ISSUE(0); CP_COMMIT();
    GU_ISSUE(1); CP_COMMIT();
    GU_ISSUE(2); CP_COMMIT();

    for (int c = 0; c < NCH; c++) {
        CP_WAIT(2);
        __syncthreads();
        if (c + 3 < NCH) GU_ISSUE(c + 3);
        CP_COMMIT();

        uint32_t stA  = smb + (uint32_t)(c % NSTG_G) * GU_STAGE;
        uint32_t stBg = stA + A_BYTES;
        uint32_t stBu = stBg + BG_BYTES;

#pragma unroll
        for (int s = 0; s < 2; s++) {           // two k16 steps per 32-chunk
            uint32_t a[2][4];
#pragma unroll
            for (int mt = 0; mt < 2; mt++)
                ldsm4(a[mt], stA + aOff + (uint32_t)(mt * 16 * A_ROWB + s * 32));
#pragma unroll
            for (int nt = 0; nt < 2; nt++) {
                uint32_t off = bOff + (uint32_t)(s * 16 * BG_ROWB + nt * 16);
                uint32_t bg[2], bu[2];
                ldsm2t(bg, stBg + off);
                ldsm2t(bu, stBu + off);
#pragma unroll
                for (int mt = 0; mt < 2; mt++) {
                    mma16(accG[mt][nt], a[mt], bg);
                    mma16(accU[mt][nt], a[mt], bu);
                }
            }
        }
    }

    // ---- epilogue: bias + clamp + SwiGLU -> fp16 g_acth ----
    const float* bge = bgu + (size_t)e * (2 * IDIM);
#pragma unroll
    for (int mt = 0; mt < 2; mt++) {
#pragma unroll
        for (int half = 0; half < 2; half++) {
            int row = wM * 32 + mt * 16 + half * 8 + gID;
            int slot = sSlot[row];
            if (slot < 0) continue;
            __half* outp = g_acth + (size_t)slot * IDIM;
#pragma unroll
            for (int nt = 0; nt < 2; nt++) {
                int col = n0 + wN * 16 + nt * 8 + 2 * tg;
                float g0 = accG[mt][nt][half * 2 + 0] + bge[col];
                float g1 = accG[mt][nt][half * 2 + 1] + bge[col + 1];
                float u0 = accU[mt][nt][half * 2 + 0] + bge[IDIM + col];
                float u1 = accU[mt][nt][half * 2 + 1] + bge[IDIM + col + 1];
                g0 = fminf(g0, LIMIT); g1 = fminf(g1, LIMIT);
                u0 = fmaxf(fminf(u0, LIMIT), -LIMIT);
                u1 = fmaxf(fminf(u1, LIMIT), -LIMIT);
                float s0 = 1.f / (1.f + expf(-ALPHA * g0));
                float s1 = 1.f / (1.f + expf(-ALPHA * g1));
                *(__half2*)(outp + col) =
                    __floats2half2_rn((u0 + 1.f) * (g0 * s0), (u1 + 1.f) * (g1 * s1));
            }
        }
    }
}

// =============== stage 2: down GEMM (fp32 B direct) + weighted red.v2 ===============
// block 128 x 64, 8 warps 4Mx2N, warp 32x32. (R14 config, measured 37.2us)
__global__ __launch_bounds__(256, 3) void down_mma(
    const float* __restrict__ Wd, const float* __restrict__ bd,
    float* __restrict__ out)
{
    int e   = blockIdx.z;
    int cnt = g_cnt[e];
    int m0  = blockIdx.y * 128;
    if (m0 >= cnt) return;
    int n0  = blockIdx.x * 64;

    extern __shared__ __align__(16) char dsm[];
    __shared__ int sSlot[128];

    int tid  = threadIdx.x;
    int wid  = tid >> 5, lane = tid & 31;
    int wM   = wid >> 1, wN = wid & 1;
    int gID  = lane >> 2, tg = lane & 3;

    for (int m = tid; m < 128; m += 256) {
        int idx = m0 + m;
        sSlot[m] = (idx < cnt) ? g_list[e * MAXP + idx] : -1;
    }
    __syncthreads();

    const float* We = Wd + (size_t)e * IDIM * HDIM;
    uint32_t smb = smem_u32(dsm);
    uint32_t aOff = (uint32_t)(wM * 32 * A_ROWB + (lane & 15) * A_ROWB + (lane >> 4) * 16);

    const __half* aSrc[2]; int aSz[2]; uint32_t aDst[2];
#pragma unroll
    for (int i = 0; i < 2; i++) {
        int idx = tid + i * 256;
        int m = idx >> 2, kq = idx & 3;
        int slot = sSlot[m];
        aSrc[i] = (slot >= 0) ? g_acth + (size_t)slot * IDIM + kq * 8 : g_acth;
        aSz[i]  = (slot >= 0) ? 16 : 0;
        aDst[i] = (uint32_t)(m * A_ROWB + kq * 16);
    }
    const float* bSrc[2]; uint32_t bDst[2];
#pragma unroll
    for (int i = 0; i < 2; i++) {
        int idx = tid + i * 256;
        int k = idx >> 4, n4 = idx & 15;
        bSrc[i] = We + (size_t)k * HDIM + n0 + n4 * 4;
        bDst[i] = (uint32_t)((k * BD_ROWW + n4 * 4) * 4);
    }

    float acc[2][4][4];
#pragma unroll
    for (int mt = 0; mt < 2; mt++)
#pragma unroll
        for (int nt = 0; nt < 4; nt++)
#pragma unroll
            for (int q = 0; q < 4; q++) acc[mt][nt][q] = 0.f;

#define DN_ISSUE(c) do {                                                       \
    uint32_t st = smb + (uint32_t)((c) % NSTG_D) * DN_STAGE;                   \
    int k0 = (c) * BK;                                                         \
    _Pragma("unroll")                                                          \
    for (int i = 0; i < 2; i++) cp16(st + aDst[i], aSrc[i] + k0, aSz[i]);      \
    _Pragma("unroll")                                                          \
    for (int i = 0; i < 2; i++)                                                \
        cp16(st + A_BYTES + bDst[i], bSrc[i] + (size_t)k0 * HDIM, 16);         \
    } while (0)

    DN_ISSUE(0); CP_COMMIT();
    DN_ISSUE(1); CP_COMMIT();
    DN_ISSUE(2); CP_COMMIT();

    int colw = wN * 32 + gID;
    for (int c = 0; c < NCH; c++) {
        CP_WAIT(2);
        __syncthreads();
        if (c + 3 < NCH) DN_ISSUE(c + 3);
        CP_COMMIT();

        uint32_t stA = smb + (uint32_t)(c % NSTG_D) * DN_STAGE;
        const float* fB = (const float*)(dsm + (c % NSTG_D) * DN_STAGE + A_BYTES);

#pragma unroll
        for (int s = 0; s < 2; s++) {
            uint32_t a[2][4];
#pragma unroll
            for (int mt = 0; mt < 2; mt++)
                ldsm4(a[mt], stA + aOff + (uint32_t)(mt * 16 * A_ROWB + s * 32));
            int kb = s * 16 + 2 * tg;
#pragma unroll
            for (int nt = 0; nt < 4; nt++) {
                int cw = colw + nt * 8;
                uint32_t b[2];
                b[0] = packh(fB[kb * BD_ROWW + cw],       fB[(kb + 1) * BD_ROWW + cw]);
                b[1] = packh(fB[(kb + 8) * BD_ROWW + cw], fB[(kb + 9) * BD_ROWW + cw]);
#pragma unroll
                for (int mt = 0; mt < 2; mt++)
                    mma16(acc[mt][nt], a[mt], b);
            }
        }
    }

    // ---- epilogue: weighted vector reduction into out ----
    const float* bde = bd + (size_t)e * HDIM;
#pragma unroll
    for (int mt = 0; mt < 2; mt++) {
#pragma unroll
        for (int half = 0; half < 2; half++) {
            int row = wM * 32 + mt * 16 + half * 8 + gID;
            int slot = sSlot[row];
            if (slot < 0) continue;
            float w = g_w[slot];
            float* outp = out + (size_t)(slot >> 1) * HDIM;
#pragma unroll
            for (int nt = 0; nt < 4; nt++) {
                int col = n0 + wN * 32 + nt * 8 + 2 * tg;
                red2(outp + col,
                     w * (acc[mt][nt][half * 2 + 0] + bde[col]),
                     w * (acc[mt][nt][half * 2 + 1] + bde[col + 1]));
            }
        }
    }
}

// ------------------------------ launch ------------------------------
extern "C" void kernel_launch(void* const* d_in, const int* in_sizes, int n_in,
                              void* d_out, int out_size)
{
    const float* x   = (const float*)d_in[0];
    const float* Wr  = (const float*)d_in[1];
    const float* br  = (const float*)d_in[2];
    const float* Wgu = (const float*)d_in[3];
    const float* bgu = (const float*)d_in[4];
    const float* Wd  = (const float*)d_in[5];
    const float* bd  = (const float*)d_in[6];
    float* out = (float*)d_out;

    const int GU_SMEM = NSTG_G * GU_STAGE;   // 61440
    const int DN_SMEM = NSTG_D * DN_STAGE;   // 75776
    cudaFuncSetAttribute(gu_mma,   cudaFuncAttributeMaxDynamicSharedMemorySize, GU_SMEM);
    cudaFuncSetAttribute(down_mma, cudaFuncAttributeMaxDynamicSharedMemorySize, DN_SMEM);

    prep_kernel<<<(WGU_N / 8 + 255) / 256, 256>>>(Wgu);
    router_kernel<<<TTOK / 8, 256>>>(x, Wr, br, out);

    dim3 ggrid(IDIM / 32, MAXP / 128, NEXP);   // (24, 32, 8)
    gu_mma<<<ggrid, 256, GU_SMEM>>>(bgu);

    dim3 dgrid(HDIM / 64, MAXP / 128, NEXP);   // (12, 32, 8)
    down_mma<<<dgrid, 256, DN_SMEM>>>(Wd, bd, out);
}

// round 16
// speedup vs baseline: 1.1385x; 1.0297x over previous
#include <cuda_runtime.h>
#include <cuda_fp16.h>
#include <math.h>
#include <stdint.h>

#define TTOK   2048
#define HDIM   768
#define NEXP   8
#define IDIM   768
#define MAXP   (TTOK*2)
#define ALPHA  1.702f
#define LIMIT  7.0f
#define BK     32
#define NCH    (HDIM / BK)   // 24
#define NSTG_G 4
#define NSTG_D 4

#define WGU_N  (NEXP * HDIM * 2 * IDIM)   // 9437184
#define WD_N   (NEXP * IDIM * HDIM)       // 4718592

// -------- scratch --------
__device__ int    g_cnt[NEXP];
__device__ int    g_list[NEXP * MAXP];
__device__ float  g_w[TTOK * 2];
__device__ __half g_xh[(size_t)TTOK * HDIM];
__device__ __half g_acth[(size_t)TTOK * 2 * IDIM];
__device__ __half g_wguh[WGU_N];
__device__ __half g_wdh[WD_N];

// ------------------------- helpers -------------------------
__device__ __forceinline__ uint32_t h2u(__half2 h) {
    union { __half2 h; uint32_t u; } v; v.h = h; return v.u;
}
__device__ __forceinline__ uint32_t packh(float lo, float hi) {
    return h2u(__floats2half2_rn(lo, hi));
}
__device__ __forceinline__ void mma16(float* d, const uint32_t* a, const uint32_t* b) {
    asm volatile(
        "mma.sync.aligned.m16n8k16.row.col.f32.f16.f16.f32 "
        "{%0,%1,%2,%3}, {%4,%5,%6,%7}, {%8,%9}, {%0,%1,%2,%3};"
        : "+f"(d[0]), "+f"(d[1]), "+f"(d[2]), "+f"(d[3])
        : "r"(a[0]), "r"(a[1]), "r"(a[2]), "r"(a[3]), "r"(b[0]), "r"(b[1]));
}
__device__ __forceinline__ uint32_t smem_u32(const void* p) {
    uint32_t a;
    asm("{ .reg .u64 t; cvta.to.shared.u64 t, %1; cvt.u32.u64 %0, t; }"
        : "=r"(a) : "l"(p));
    return a;
}
__device__ __forceinline__ void cp16(uint32_t dst, const void* src, int sz) {
    asm volatile("cp.async.cg.shared.global [%0], [%1], 16, %2;"
                 :: "r"(dst), "l"(src), "r"(sz));
}
#define CP_COMMIT() asm volatile("cp.async.commit_group;" ::: "memory")
#define CP_WAIT(n)  asm volatile("cp.async.wait_group %0;" :: "n"(n) : "memory")
__device__ __forceinline__ void ldsm4(uint32_t* r, uint32_t addr) {
    asm volatile("ldmatrix.sync.aligned.m8n8.x4.shared.b16 {%0,%1,%2,%3}, [%4];"
                 : "=r"(r[0]), "=r"(r[1]), "=r"(r[2]), "=r"(r[3]) : "r"(addr));
}
__device__ __forceinline__ void ldsm2t(uint32_t* r, uint32_t addr) {
    asm volatile("ldmatrix.sync.aligned.m8n8.x2.trans.shared.b16 {%0,%1}, [%2];"
                 : "=r"(r[0]), "=r"(r[1]) : "r"(addr));
}
__device__ __forceinline__ void red2(float* p, float v0, float v1) {
    asm volatile("red.global.add.v2.f32 [%0], {%1, %2};"
                 :: "l"(p), "f"(v0), "f"(v1) : "memory");
}

// A tile: 128 x 32 halves, row 64B + 16 pad = 80B
#define A_ROWB   80
#define A_BYTES  (128 * A_ROWB)        // 10240
// gu B tile (per plane): 32 x 64 halves, row 128B + 16 = 144B
#define BG_ROWB  144
#define BG_BYTES (32 * BG_ROWB)        // 4608
#define GU_STAGE (A_BYTES + 2 * BG_BYTES)   // 19456
// down B tile: 32 x 128 halves, row 256B + 16 = 272B
#define BD_ROWB  272
#define BD_BYTES (32 * BD_ROWB)        // 8704
#define DN_STAGE (A_BYTES + BD_BYTES)       // 18944

// ---------------- prep: weights -> fp16 (+ zero counters) ----------------
__global__ __launch_bounds__(256) void prep_kernel(
    const float* __restrict__ Wgu, const float* __restrict__ Wd)
{
    size_t idx = (size_t)blockIdx.x * 256 + threadIdx.x;
    if (idx < NEXP) g_cnt[idx] = 0;
    const size_t n1 = WGU_N / 8, n2 = WD_N / 8;
    const float4* src;
    uint4* dst;
    size_t j;
    if (idx < n1)          { src = (const float4*)Wgu; dst = (uint4*)g_wguh; j = idx; }
    else if (idx < n1 + n2){ src = (const float4*)Wd;  dst = (uint4*)g_wdh;  j = idx - n1; }
    else return;
    float4 a = src[j * 2], b = src[j * 2 + 1];
    dst[j] = make_uint4(packh(a.x, a.y), packh(a.z, a.w),
                        packh(b.x, b.y), packh(b.z, b.w));
}

// ------------------- router (+ zero out rows, + x -> fp16) -------------------
__global__ __launch_bounds__(256) void router_kernel(
    const float* __restrict__ x, const float* __restrict__ Wr,
    const float* __restrict__ br, float* __restrict__ out)
{
    {
        float4* ob = (float4*)(out + (size_t)blockIdx.x * 8 * HDIM);
#pragma unroll
        for (int i = 0; i < 6; i++)
            ob[threadIdx.x + i * 256] = make_float4(0.f, 0.f, 0.f, 0.f);
    }

    int warp = threadIdx.x >> 5;
    int lane = threadIdx.x & 31;
    int t = blockIdx.x * 8 + warp;

    const float4* xr = (const float4*)(x + (size_t)t * HDIM);
    __half2* xo = (__half2*)(g_xh + (size_t)t * HDIM);
    float acc[NEXP];
#pragma unroll
    for (int e = 0; e < NEXP; e++) acc[e] = 0.f;

#pragma unroll
    for (int i = 0; i < 6; i++) {
        int h4 = lane + i * 32;
        float4 xv = xr[h4];
        xo[h4 * 2]     = __floats2half2_rn(xv.x, xv.y);
        xo[h4 * 2 + 1] = __floats2half2_rn(xv.z, xv.w);
        const float* w = Wr + h4 * 4 * NEXP;
#pragma unroll
        for (int e = 0; e < NEXP; e++) {
            float s = fmaf(xv.x, w[e], 0.f);
            s = fmaf(xv.y, w[e + 8], s);
            s = fmaf(xv.z, w[e + 16], s);
            s = fmaf(xv.w, w[e + 24], s);
            acc[e] += s;
        }
    }
#pragma unroll
    for (int e = 0; e < NEXP; e++) {
#pragma unroll
        for (int o = 16; o > 0; o >>= 1)
            acc[e] += __shfl_xor_sync(0xffffffffu, acc[e], o);
    }
    if (lane == 0) {
#pragma unroll
        for (int e = 0; e < NEXP; e++) acc[e] += br[e];

        int i0 = 0; float v0 = acc[0];
#pragma unroll
        for (int e = 1; e < NEXP; e++)
            if (acc[e] > v0) { v0 = acc[e]; i0 = e; }
        int i1 = -1; float v1 = -INFINITY;
#pragma unroll
        for (int e = 0; e < NEXP; e++)
            if (e != i0 && acc[e] > v1) { v1 = acc[e]; i1 = e; }

        float s1 = expf(v1 - v0);
        float d  = 1.f + s1;
        g_w[t * 2 + 0] = 1.f / d;
        g_w[t * 2 + 1] = s1 / d;

        int p0 = atomicAdd(&g_cnt[i0], 1);
        g_list[i0 * MAXP + p0] = t * 2;
        int p1 = atomicAdd(&g_cnt[i1], 1);
        g_list[i1 * MAXP + p1] = t * 2 + 1;
    }
}

// =============== stage 1: fp16 gate/up GEMM + SwiGLU ===============
// block 128M x (64 gate | 64 up), 8 warps 4Mx2N, warp 32M x 32N per plane.
__global__ __launch_bounds__(256, 2) void gu_mma(const float* __restrict__ bgu)
{
    int e   = blockIdx.z;
    int cnt = g_cnt[e];
    int m0  = blockIdx.y * 128;
    if (m0 >= cnt) return;
    int n0  = blockIdx.x * 64;   // per-plane column base

    extern __shared__ __align__(16) char dsm[];
    __shared__ int sSlot[128];

    int tid  = threadIdx.x;
    int wid  = tid >> 5, lane = tid & 31;
    int wM   = wid >> 1, wN = wid & 1;
    int gID  = lane >> 2, tg = lane & 3;

    for (int m = tid; m < 128; m += 256) {
        int idx = m0 + m;
        sSlot[m] = (idx < cnt) ? g_list[e * MAXP + idx] : -1;
    }
    __syncthreads();

    const __half* Wg = g_wguh + (size_t)e * HDIM * (2 * IDIM);
    uint32_t smb = smem_u32(dsm);
    uint32_t aOff = (uint32_t)(wM * 32 * A_ROWB + (lane & 15) * A_ROWB + (lane >> 4) * 16);
    uint32_t bOff = (uint32_t)((lane & 15) * BG_ROWB + wN * 64);

    const __half* aSrc[2]; int aSz[2]; uint32_t aDst[2];
#pragma unroll
    for (int i = 0; i < 2; i++) {
        int idx = tid + i * 256;
        int m = idx >> 2, kq = idx & 3;
        int slot = sSlot[m];
        aSrc[i] = (slot >= 0) ? g_xh + (size_t)(slot >> 1) * HDIM + kq * 8 : g_xh;
        aSz[i]  = (slot >= 0) ? 16 : 0;
        aDst[i] = (uint32_t)(m * A_ROWB + kq * 16);
    }
    // B: 2 planes x 32 k-rows x 128B = 512 cp16 -> 2 per thread
    const __half* bSrc[2]; uint32_t bDst[2];
#pragma unroll
    for (int i = 0; i < 2; i++) {
        int idx = tid + i * 256;
        int plane = idx >> 8, k = (idx >> 3) & 31, n8 = idx & 7;
        bSrc[i] = Wg + (size_t)k * (2 * IDIM) + plane * IDIM + n0 + n8 * 8;
        bDst[i] = (uint32_t)(plane * BG_BYTES + k * BG_ROWB + n8 * 16);
    }

    float accG[2][4][4], accU[2][4][4];
#pragma unroll
    for (int mt = 0; mt < 2; mt++)
#pragma unroll
        for (int nt = 0; nt < 4; nt++)
#pragma unroll
            for (int q = 0; q < 4; q++) { accG[mt][nt][q] = 0.f; accU[mt][nt][q] = 0.f; }

#define GU_ISSUE(c) do {                                                       \
    uint32_t st = smb + (uint32_t)((c) % NSTG_G) * GU_STAGE;                   \
    int k0 = (c) * BK;                                                         \
    _Pragma("unroll")                                                          \
    for (int i = 0; i < 2; i++) cp16(st + aDst[i], aSrc[i] + k0, aSz[i]);      \
    _Pragma("unroll")                                                          \
    for (int i = 0; i < 2; i++)                                                \
        cp16(st + A_BYTES + bDst[i], bSrc[i] + (size_t)k0 * (2 * IDIM), 16);   \
    } while (0)

    GU_ISSUE(0); CP_COMMIT();
    GU_ISSUE(1); CP_COMMIT();
    GU_ISSUE(2); CP_COMMIT();

    for (int c = 0; c < NCH; c++) {
        CP_WAIT(2);
        __syncthreads();
        if (c + 3 < NCH) GU_ISSUE(c + 3);
        CP_COMMIT();

        uint32_t stA  = smb + (uint32_t)(c % NSTG_G) * GU_STAGE;
        uint32_t stBg = stA + A_BYTES;
        uint32_t stBu = stBg + BG_BYTES;

#pragma unroll
        for (int s = 0; s < 2; s++) {
            uint32_t a[2][4];
#pragma unroll
            for (int mt = 0; mt < 2; mt++)
                ldsm4(a[mt], stA + aOff + (uint32_t)(mt * 16 * A_ROWB + s * 32));
#pragma unroll
            for (int nt = 0; nt < 4; nt++) {
                uint32_t off = bOff + (uint32_t)(s * 16 * BG_ROWB + nt * 16);
                uint32_t bg[2], bu[2];
                ldsm2t(bg, stBg + off);
                ldsm2t(bu, stBu + off);
#pragma unroll
                for (int mt = 0; mt < 2; mt++) {
                    mma16(accG[mt][nt], a[mt], bg);
                    mma16(accU[mt][nt], a[mt], bu);
                }
            }
        }
    }

    // ---- epilogue: bias + clamp + SwiGLU -> fp16 g_acth ----
    const float* bge = bgu + (size_t)e * (2 * IDIM);
#pragma unroll
    for (int mt = 0; mt < 2; mt++) {
#pragma unroll
        for (int half = 0; half < 2; half++) {
            int row = wM * 32 + mt * 16 + half * 8 + gID;
            int slot = sSlot[row];
            if (slot < 0) continue;
            __half* outp = g_acth + (size_t)slot * IDIM;
#pragma unroll
            for (int nt = 0; nt < 4; nt++) {
                int col = n0 + wN * 32 + nt * 8 + 2 * tg;
                float g0 = accG[mt][nt][half * 2 + 0] + bge[col];
                float g1 = accG[mt][nt][half * 2 + 1] + bge[col + 1];
                float u0 = accU[mt][nt][half * 2 + 0] + bge[IDIM + col];
                float u1 = accU[mt][nt][half * 2 + 1] + bge[IDIM + col + 1];
                g0 = fminf(g0, LIMIT); g1 = fminf(g1, LIMIT);
                u0 = fmaxf(fminf(u0, LIMIT), -LIMIT);
                u1 = fmaxf(fminf(u1, LIMIT), -LIMIT);
                float s0 = 1.f / (1.f + expf(-ALPHA * g0));
                float s1 = 1.f / (1.f + expf(-ALPHA * g1));
                *(__half2*)(outp + col) =
                    __floats2half2_rn((u0 + 1.f) * (g0 * s0), (u1 + 1.f) * (g1 * s1));
            }
        }
    }
}

// =============== stage 2: fp16 down GEMM + weighted red.v2 combine ===============
// block 128M x 128N, 8 warps 4Mx2N, warp 32M x 64N.
__global__ __launch_bounds__(256, 2) void down_mma(
    const float* __restrict__ bd, float* __restrict__ out)
{
    int e   = blockIdx.z;
    int cnt = g_cnt[e];
    int m0  = blockIdx.y * 128;
    if (m0 >= cnt) return;
    int n0  = blockIdx.x * 128;

    extern __shared__ __align__(16) char dsm[];
    __shared__ int sSlot[128];

    int tid  = threadIdx.x;
    int wid  = tid >> 5, lane = tid & 31;
    int wM   = wid >> 1, wN = wid & 1;
    int gID  = lane >> 2, tg = lane & 3;

    for (int m = tid; m < 128; m += 256) {
        int idx = m0 + m;
        sSlot[m] = (idx < cnt) ? g_list[e * MAXP + idx] : -1;
    }
    __syncthreads();

    const __half* We = g_wdh + (size_t)e * IDIM * HDIM;
    uint32_t smb = smem_u32(dsm);
    uint32_t aOff = (uint32_t)(wM * 32 * A_ROWB + (lane & 15) * A_ROWB + (lane >> 4) * 16);
    uint32_t bOff = (uint32_t)((lane & 15) * BD_ROWB + wN * 128);

    const __half* aSrc[2]; int aSz[2]; uint32_t aDst[2];
#pragma unroll
    for (int i = 0; i < 2; i++) {
        int idx = tid + i * 256;
        int m = idx >> 2, kq = idx & 3;
        int slot = sSlot[m];
        aSrc[i] = (slot >= 0) ? g_acth + (size_t)slot * IDIM + kq * 8 : g_acth;
        aSz[i]  = (slot >= 0) ? 16 : 0;
        aDst[i] = (uint32_t)(m * A_ROWB + kq * 16);
    }
    // B: 32 k-rows x 256B = 512 cp16 -> 2 per thread
    const __half* bSrc[2]; uint32_t bDst[2];
#pragma unroll
    for (int i = 0; i < 2; i++) {
        int idx = tid + i * 256;
        int k = idx >> 4, n8 = idx & 15;
        bSrc[i] = We + (size_t)k * HDIM + n0 + n8 * 8;
        bDst[i] = (uint32_t)(k * BD_ROWB + n8 * 16);
    }

    float acc[2][8][4];
#pragma unroll
    for (int mt = 0; mt < 2; mt++)
#pragma unroll
        for (int nt = 0; nt < 8; nt++)
#pragma unroll
            for (int q = 0; q < 4; q++) acc[mt][nt][q] = 0.f;

#define DN_ISSUE(c) do {                                                       \
    uint32_t st = smb + (uint32_t)((c) % NSTG_D) * DN_STAGE;                   \
    int k0 = (c) * BK;                                                         \
    _Pragma("unroll")                                                          \
    for (int i = 0; i < 2; i++) cp16(st + aDst[i], aSrc[i] + k0, aSz[i]);      \
    _Pragma("unroll")                                                          \
    for (int i = 0; i < 2; i++)                                                \
        cp16(st + A_BYTES + bDst[i], bSrc[i] + (size_t)k0 * HDIM, 16);         \
    } while (0)

    DN_ISSUE(0); CP_COMMIT();
    DN_ISSUE(1); CP_COMMIT();
    DN_ISSUE(2); CP_COMMIT();

    for (int c = 0; c < NCH; c++) {
        CP_WAIT(2);
        __syncthreads();
        if (c + 3 < NCH) DN_ISSUE(c + 3);
        CP_COMMIT();

        uint32_t stA = smb + (uint32_t)(c % NSTG_D) * DN_STAGE;
        uint32_t stB = stA + A_BYTES;

#pragma unroll
        for (int s = 0; s < 2; s++) {
            uint32_t a[2][4];
#pragma unroll
            for (int mt = 0; mt < 2; mt++)
                ldsm4(a[mt], stA + aOff + (uint32_t)(mt * 16 * A_ROWB + s * 32));
#pragma unroll
            for (int nt = 0; nt < 8; nt++) {
                uint32_t b[2];
                ldsm2t(b, stB + bOff + (uint32_t)(s * 16 * BD_ROWB + nt * 16));
#pragma unroll
                for (int mt = 0; mt < 2; mt++)
                    mma16(acc[mt][nt], a[mt], b);
            }
        }
    }

    // ---- epilogue: weighted vector reduction into out ----
    const float* bde = bd + (size_t)e * HDIM;
#pragma unroll
    for (int mt = 0; mt < 2; mt++) {
#pragma unroll
        for (int half = 0; half < 2; half++) {
            int row = wM * 32 + mt * 16 + half * 8 + gID;
            int slot = sSlot[row];
            if (slot < 0) continue;
            float w = g_w[slot];
            float* outp = out + (size_t)(slot >> 1) * HDIM;
#pragma unroll
            for (int nt = 0; nt < 8; nt++) {
                int col = n0 + wN * 64 + nt * 8 + 2 * tg;
                red2(outp + col,
                     w * (acc[mt][nt][half * 2 + 0] + bde[col]),
                     w * (acc[mt][nt][half * 2 + 1] + bde[col + 1]));
            }
        }
    }
}

// ------------------------------ launch ------------------------------
extern "C" void kernel_launch(void* const* d_in, const int* in_sizes, int n_in,
                              void* d_out, int out_size)
{
    const float* x   = (const float*)d_in[0];
    const float* Wr  = (const float*)d_in[1];
    const float* br  = (const float*)d_in[2];
    const float* Wgu = (const float*)d_in[3];
    const float* bgu = (const float*)d_in[4];
    const float* Wd  = (const float*)d_in[5];
    const float* bd  = (const float*)d_in[6];
    float* out = (float*)d_out;

    const int GU_SMEM = NSTG_G * GU_STAGE;   // 77824
    const int DN_SMEM = NSTG_D * DN_STAGE;   // 75776
    cudaFuncSetAttribute(gu_mma,   cudaFuncAttributeMaxDynamicSharedMemorySize, GU_SMEM);
    cudaFuncSetAttribute(down_mma, cudaFuncAttributeMaxDynamicSharedMemorySize, DN_SMEM);

    const size_t PREP_T = (WGU_N + WD_N) / 8;
    prep_kernel<<<(int)((PREP_T + 255) / 256), 256>>>(Wgu, Wd);
    router_kernel<<<TTOK / 8, 256>>>(x, Wr, br, out);

    dim3 ggrid(IDIM / 64, MAXP / 128, NEXP);    // (12, 32, 8)
    gu_mma<<<ggrid, 256, GU_SMEM>>>(bgu);

    dim3 dgrid(HDIM / 128, MAXP / 128, NEXP);   // (6, 32, 8)
    down_mma<<<dgrid, 256, DN_SMEM>>>(bd, out);
}